// round 13
// baseline (speedup 1.0000x reference)
#include <cuda_runtime.h>
#include <math.h>

#define T_   1024
#define B_   32
#define IN_  1024
#define H_   512
#define TB_  (T_ * B_)

typedef unsigned long long ull;

// ---------------- static device scratch (no runtime alloc allowed) ----------
__device__ float g_xin[2][(size_t)TB_ * H_];   // per-direction input projections (biases folded)
__device__ float g_seq[(size_t)TB_ * 2 * H_];  // layer-0 output, [t][b][2H]

// ---------------- f32x2 helpers (ptxas never emits FFMA2 from C++) ----------
__device__ __forceinline__ ull pk2(float lo, float hi) {
    ull r; asm("mov.b64 %0, {%1,%2};" : "=l"(r) : "f"(lo), "f"(hi)); return r;
}
__device__ __forceinline__ void upk2(ull v, float& lo, float& hi) {
    asm("mov.b64 {%0,%1}, %2;" : "=f"(lo), "=f"(hi) : "l"(v));
}
__device__ __forceinline__ void fma2(ull& d, ull a, ull b) {
    asm("fma.rn.f32x2 %0, %1, %2, %0;" : "+l"(d) : "l"(a), "l"(b));
}
__device__ __forceinline__ unsigned smem_u32(const void* p) {
    unsigned a;
    asm("{ .reg .u64 t; cvta.to.shared.u64 t, %1; cvt.u32.u64 %0, t; }" : "=r"(a) : "l"(p));
    return a;
}
// DSMEM push: map local smem addr to peer rank, scalar store
__device__ __forceinline__ void dsmem_st(unsigned laddr, unsigned rank, float v) {
    asm volatile(
        "{\n\t.reg .u32 ra;\n\t"
        "mapa.shared::cluster.u32 ra, %0, %1;\n\t"
        "st.shared::cluster.f32 [ra], %2;\n\t}"
        :: "r"(laddr), "r"(rank), "f"(v) : "memory");
}

// ---------------------------------------------------------------------------
// Input-projection GEMM (register-prefetch pipelined) — unchanged (proven).
// ---------------------------------------------------------------------------
__global__ __launch_bounds__(256, 2) void gemm_kernel(
    const float* __restrict__ x,
    const float* __restrict__ w_ih,
    const float* __restrict__ b_ih,
    const float* __restrict__ b_hh,
    const float* __restrict__ noise_in,
    int layer)
{
    __shared__ float As[16 * 132];   // [k][m], padded
    __shared__ float Bs[16 * 68];    // [k][n], padded

    const int tid  = threadIdx.x;
    const int cell = blockIdx.z;
    const int cabs = layer * 2 + cell;
    const int n0   = blockIdx.x * 64;
    const int m0   = blockIdx.y * 128;
    const int tx   = tid & 15;
    const int ty   = tid >> 4;
    const int msub = ty * 8;
    const int nsub = tx * 4;

    const float* A  = (layer == 0) ? x : g_seq;
    const float* nz = noise_in + (size_t)cabs * B_ * IN_;
    const float* wb = w_ih + (size_t)cabs * H_ * IN_;
    float* outp = g_xin[cell];

    ull acc[4][4];
#pragma unroll
    for (int i = 0; i < 4; i++)
#pragma unroll
        for (int j = 0; j < 4; j++) acc[i][j] = 0ull;

    const int e0 = tid, e1 = tid + 256;
    const int row0 = e0 >> 2, kq0 = (e0 & 3) * 4;
    const int row1 = e1 >> 2, kq1 = (e1 & 3) * 4;
    size_t ab0, ab1;
    if (layer == 0) {   // m = t*B + b ; x addr = b*(T*IN) + t*IN
        ab0 = (size_t)(row0 & 31) * ((size_t)T_ * IN_) + (size_t)(m0 / 32 + (row0 >> 5)) * IN_;
        ab1 = (size_t)(row1 & 31) * ((size_t)T_ * IN_) + (size_t)(m0 / 32 + (row1 >> 5)) * IN_;
    } else {
        ab0 = (size_t)(m0 + row0) * IN_;
        ab1 = (size_t)(m0 + row1) * IN_;
    }
    const size_t nb0 = (size_t)(row0 & 31) * IN_;
    const size_t nb1 = (size_t)(row1 & 31) * IN_;
    const int brow = tid >> 2, bkq = (tid & 3) * 4;
    const float* wrow = wb + (size_t)(n0 + brow) * IN_ + bkq;

    float4 xv0 = *(const float4*)(A + ab0 + kq0);
    float4 nv0 = *(const float4*)(nz + nb0 + kq0);
    float4 xv1 = *(const float4*)(A + ab1 + kq1);
    float4 nv1 = *(const float4*)(nz + nb1 + kq1);
    float4 wv0 = *(const float4*)(wrow);

    for (int k0 = 0; k0 < IN_; k0 += 16) {
        As[(kq0 + 0) * 132 + row0] = xv0.x * nv0.x;
        As[(kq0 + 1) * 132 + row0] = xv0.y * nv0.y;
        As[(kq0 + 2) * 132 + row0] = xv0.z * nv0.z;
        As[(kq0 + 3) * 132 + row0] = xv0.w * nv0.w;
        As[(kq1 + 0) * 132 + row1] = xv1.x * nv1.x;
        As[(kq1 + 1) * 132 + row1] = xv1.y * nv1.y;
        As[(kq1 + 2) * 132 + row1] = xv1.z * nv1.z;
        As[(kq1 + 3) * 132 + row1] = xv1.w * nv1.w;
        Bs[(bkq + 0) * 68 + brow] = wv0.x;
        Bs[(bkq + 1) * 68 + brow] = wv0.y;
        Bs[(bkq + 2) * 68 + brow] = wv0.z;
        Bs[(bkq + 3) * 68 + brow] = wv0.w;
        __syncthreads();

        const int kn = k0 + 16;
        if (kn < IN_) {
            xv0 = *(const float4*)(A + ab0 + kn + kq0);
            nv0 = *(const float4*)(nz + nb0 + kn + kq0);
            xv1 = *(const float4*)(A + ab1 + kn + kq1);
            nv1 = *(const float4*)(nz + nb1 + kn + kq1);
            wv0 = *(const float4*)(wrow + kn);
        }

#pragma unroll
        for (int k = 0; k < 16; k++) {
            float4 b4 = *(const float4*)&Bs[k * 68 + nsub];
            ull bd0 = pk2(b4.x, b4.x);
            ull bd1 = pk2(b4.y, b4.y);
            ull bd2 = pk2(b4.z, b4.z);
            ull bd3 = pk2(b4.w, b4.w);
#pragma unroll
            for (int mp = 0; mp < 4; mp++) {
                ull au = *(const ull*)&As[k * 132 + msub + 2 * mp];
                fma2(acc[mp][0], au, bd0);
                fma2(acc[mp][1], au, bd1);
                fma2(acc[mp][2], au, bd2);
                fma2(acc[mp][3], au, bd3);
            }
        }
        __syncthreads();
    }

    float bi[4];
#pragma unroll
    for (int nn = 0; nn < 4; nn++) {
        int n = n0 + nsub + nn;
        bi[nn] = b_ih[cabs * H_ + n] + b_hh[cabs * H_ + n];
    }
#pragma unroll
    for (int mp = 0; mp < 4; mp++) {
        float lo[4], hi[4];
#pragma unroll
        for (int nn = 0; nn < 4; nn++) upk2(acc[mp][nn], lo[nn], hi[nn]);
        float4 v0 = make_float4(lo[0] + bi[0], lo[1] + bi[1], lo[2] + bi[2], lo[3] + bi[3]);
        float4 v1 = make_float4(hi[0] + bi[0], hi[1] + bi[1], hi[2] + bi[2], hi[3] + bi[3]);
        size_t r0 = (size_t)(m0 + msub + 2 * mp) * H_ + n0 + nsub;
        *(float4*)(outp + r0)      = v0;
        *(float4*)(outp + r0 + H_) = v1;
    }
}

// ---------------------------------------------------------------------------
// Recurrent scan v7: R9's proven shell (256 threads, combined cluster
// arrive+wait per step) with a ZERO-__syncthreads step body:
//  - lane map: kp = lane>>3 (K partition / owned batch), hs = lane&7,
//    h = h0 + warp*8 + hs  -> the 4 split-K partials of each (b,h) live in
//    ONE warp and reduce via 2x shfl.bfly (no smem round-trip, no barrier).
//  - every thread then owns exactly ONE output (b=kp, h): tanh (fast exp
//    form), local hbuf write, 7 DSMEM pushes, STG.
//  - combined cluster barrier orders pushes + local smem for the next step.
// ---------------------------------------------------------------------------
__global__ __launch_bounds__(256, 1) __cluster_dims__(8, 1, 1)
void recur_kernel(
    const float* __restrict__ w_hh,
    const float* __restrict__ noise_h,
    const float* __restrict__ mask,
    float* __restrict__ out,      // d_out: [B,T,2H] (layer 1 writes here)
    float* __restrict__ hn,       // d_out + B*T*2H: [L*D,B,H]
    int layer)
{
    __shared__ float hbuf[2][4 * 512];        // full h*nh vector, double buffered (16KB)

    const int tid  = threadIdx.x;
    const int bx   = blockIdx.x;
    const int dir  = bx >> 6;                 // 0 fwd, 1 bwd
    const int rank = bx & 7;                  // cluster rank == h-slice
    const int grp  = (bx >> 3) & 7;           // batch group
    const int b0   = grp * 4;
    const int h0   = rank * 64;
    const int w    = tid >> 5;                // warp (0..7)
    const int lane = tid & 31;
    const int kp   = lane >> 3;               // K partition AND owned batch
    const int hs   = lane & 7;
    const int h    = h0 + w * 8 + hs;         // owned h column
    const int c    = layer * 2 + dir;

    const unsigned hb_a = smem_u32(&hbuf[0][0]);

    // W_hh slice in registers: w[h][kp*128 .. +128) as 32 aligned f32x2 pairs
    union F4U2 { float4 f; ulonglong2 u; };
    ulonglong2 wu[32];
    {
        const float4* wp = (const float4*)(w_hh + ((size_t)c * H_ + h) * H_ + kp * 128);
#pragma unroll
        for (int i = 0; i < 32; i++) { F4U2 t; t.f = wp[i]; wu[i] = t.u; }
    }

    // per-thread recurrent state for output (b=kp, h)
    const float nh = noise_h[((size_t)c * B_ + b0 + kp) * H_ + h];
    float hprev = 0.0f;
    const float* xin = g_xin[dir];
    const unsigned my_off = (unsigned)(kp * 512 + h) * 4u;

    for (int t = 0; t < T_; t++) {
        const int ta = dir ? (T_ - 1 - t) : t;

        // prefetch xin + mask (L2 latency hidden by the FMA phase below)
        const float xv = __ldg(xin + ((size_t)ta * B_ + b0 + kp) * H_ + h);
        const float mt = __ldg(mask + (size_t)(b0 + kp) * T_ + ta);

        // dot products over our K slice (local hbuf, broadcast LDS.128)
        ull acc[4] = {0ull, 0ull, 0ull, 0ull};
        if (t > 0) {
            const float4* hb = (const float4*)&hbuf[t & 1][0];
#pragma unroll
            for (int i = 0; i < 32; i++) {
                ulonglong2 w2 = wu[i];
#pragma unroll
                for (int b = 0; b < 4; b++) {
                    F4U2 q; q.f = hb[b * 128 + kp * 32 + i];
                    fma2(acc[b], q.u.x, w2.x);
                    fma2(acc[b], q.u.y, w2.y);
                }
            }
        }
        // collapse f32x2 lanes, then butterfly-reduce the 4 kp partials
        // (lane bits 3,4 index kp) — every lane ends with full sums.
        float s0, s1, s2, s3;
        { float lo, hi;
          upk2(acc[0], lo, hi); s0 = lo + hi;
          upk2(acc[1], lo, hi); s1 = lo + hi;
          upk2(acc[2], lo, hi); s2 = lo + hi;
          upk2(acc[3], lo, hi); s3 = lo + hi; }
        s0 += __shfl_xor_sync(0xffffffffu, s0, 8);
        s1 += __shfl_xor_sync(0xffffffffu, s1, 8);
        s2 += __shfl_xor_sync(0xffffffffu, s2, 8);
        s3 += __shfl_xor_sync(0xffffffffu, s3, 8);
        s0 += __shfl_xor_sync(0xffffffffu, s0, 16);
        s1 += __shfl_xor_sync(0xffffffffu, s1, 16);
        s2 += __shfl_xor_sync(0xffffffffu, s2, 16);
        s3 += __shfl_xor_sync(0xffffffffu, s3, 16);

        // this thread's output is batch b = kp
        const float rec  = (kp == 0) ? s0 : (kp == 1) ? s1 : (kp == 2) ? s2 : s3;
        const float z    = xv + rec;                       // biases folded in xin
        const float e    = __expf(2.0f * z);               // saturates to ±1 at inf/0
        const float hnew = 1.0f - __fdividef(2.0f, e + 1.0f);
        const float hcur = hnew * mt + hprev * (1.0f - mt);
        hprev = hcur;
        const float v = hcur * nh;
        const int nb = (t + 1) & 1;
        hbuf[nb][kp * 512 + h] = v;                        // own slice, local
        const unsigned dst = hb_a + (unsigned)(nb * 8192) + my_off;
#pragma unroll
        for (unsigned r = 0; r < 8; r++)
            if (r != (unsigned)rank) dsmem_st(dst, r, v);  // 7 remote pushes
        if (layer == 0)
            g_seq[((size_t)ta * B_ + b0 + kp) * 1024 + dir * 512 + h] = hcur;
        else
            out[((size_t)(b0 + kp) * T_ + ta) * 1024 + dir * 512 + h] = hcur;

        // combined cluster barrier (R9-proven): releases pushes + local
        // smem writes, gates every CTA's next step. No __syncthreads needed.
        asm volatile("barrier.cluster.arrive.aligned;" ::: "memory");
        asm volatile("barrier.cluster.wait.aligned;"   ::: "memory");
    }

    // after the final barrier no peer can push into our smem
    hn[((size_t)c * B_ + b0 + kp) * H_ + h] = hprev;
}

// ---------------------------------------------------------------------------
extern "C" void kernel_launch(void* const* d_in, const int* in_sizes, int n_in,
                              void* d_out, int out_size) {
    const float* x        = (const float*)d_in[0];
    const float* mask     = (const float*)d_in[1];
    const float* w_ih     = (const float*)d_in[2];
    const float* w_hh     = (const float*)d_in[3];
    const float* b_ih     = (const float*)d_in[4];
    const float* b_hh     = (const float*)d_in[5];
    const float* noise_in = (const float*)d_in[6];
    const float* noise_h  = (const float*)d_in[7];
    float* out = (float*)d_out;                       // [B,T,2H]
    float* hn  = out + (size_t)B_ * T_ * 2 * H_;      // [L*D,B,H]

    dim3 gg(H_ / 64, TB_ / 128, 2);                   // (8, 256, 2)

    gemm_kernel<<<gg, 256>>>(x, w_ih, b_ih, b_hh, noise_in, 0);
    recur_kernel<<<128, 256>>>(w_hh, noise_h, mask, out, hn, 0);
    gemm_kernel<<<gg, 256>>>(x, w_ih, b_ih, b_hh, noise_in, 1);
    recur_kernel<<<128, 256>>>(w_hh, noise_h, mask, out, hn, 1);
}